// round 17
// baseline (speedup 1.0000x reference)
#include <cuda_runtime.h>
#include <cuda_bf16.h>
#include <math.h>

#define N_NODES   100000
#define N_PAD     100032   // 1563 * 64 (GEMM block rows)
#define N_EDGES   1600000
#define D         128
#define N_GRAPHS  128
#define N_CLASSES 10

// ---------------- scratch (static device globals; no allocs) ----------------
// g_fb0 / g_fb1: ping-pong bf16 feature buffers (fused kernel can't write
// the buffer it gathers from).
__device__ __align__(16) __nv_bfloat16 g_fb0[(size_t)N_PAD * D];
__device__ __align__(16) __nv_bfloat16 g_fb1[(size_t)N_PAD * D];
__device__ float g_dinv[N_NODES];
__device__ int   g_degi[N_NODES];
__device__ int   g_off [N_NODES + 1];
__device__ int   g_cur [N_NODES];
__device__ __align__(8) int2 g_csr[N_EDGES];                 // {src, norm bits}
__device__ __align__(16) float g_sums[N_GRAPHS * D];
__device__ int   g_end [N_GRAPHS];
__device__ int   g_bsum[391];
__device__ int   g_bpre[391];

// ---------------- prep: zero + boundaries + x->bf16 (one launch) ----------
__global__ void prep_kernel(const int* __restrict__ batch,
                            const float* __restrict__ X,
                            __nv_bfloat16* __restrict__ Xb) {
    int i = blockIdx.x * blockDim.x + threadIdx.x;
    if (i < N_NODES * 32) {                    // cvt: float4 -> bf16x4
        float4 v = ((const float4*)X)[i];
        __nv_bfloat162 lo = __float22bfloat162_rn(make_float2(v.x, v.y));
        __nv_bfloat162 hi = __float22bfloat162_rn(make_float2(v.z, v.w));
        uint2 u;
        u.x = *reinterpret_cast<unsigned*>(&lo);
        u.y = *reinterpret_cast<unsigned*>(&hi);
        ((uint2*)Xb)[i] = u;
    }
    if (i < N_NODES) {
        g_degi[i] = 0;
        int b  = batch[i];
        int bn = (i + 1 < N_NODES) ? batch[i + 1] : N_GRAPHS;
        for (int g = b; g < bn; g++) g_end[g] = i + 1;
        if (i == 0)
            for (int g = 0; g < b; g++) g_end[g] = 0;
    }
    if (i < N_GRAPHS * D) g_sums[i] = 0.0f;
}

__global__ void hist_kernel(const int* __restrict__ dst) {
    int e = blockIdx.x * blockDim.x + threadIdx.x;
    if (e < N_EDGES) atomicAdd(&g_degi[dst[e]], 1);
}

// ---- 3-phase parallel scan over g_degi -> g_off / g_cur (+dinv fold) ----
__global__ void blockred_kernel() {           // grid 391 x 256
    __shared__ int sh[256];
    int t = threadIdx.x;
    int i = blockIdx.x * 256 + t;
    sh[t] = (i < N_NODES) ? g_degi[i] : 0;
    __syncthreads();
    for (int ofs = 128; ofs > 0; ofs >>= 1) {
        if (t < ofs) sh[t] += sh[t + ofs];
        __syncthreads();
    }
    if (t == 0) g_bsum[blockIdx.x] = sh[0];
}

__global__ void bscan_kernel() {              // 1 block x 512
    __shared__ int sh[512];
    int t = threadIdx.x;
    int v = (t < 391) ? g_bsum[t] : 0;
    sh[t] = v;
    __syncthreads();
    for (int ofs = 1; ofs < 512; ofs <<= 1) {
        int u = (t >= ofs) ? sh[t - ofs] : 0;
        __syncthreads();
        sh[t] += u;
        __syncthreads();
    }
    if (t < 391) g_bpre[t] = sh[t] - v;
    if (t == 0) g_off[N_NODES] = N_EDGES;
}

__global__ void blockscan_kernel() {          // grid 391 x 256; also dinv
    __shared__ int sh[256];
    int t = threadIdx.x;
    int i = blockIdx.x * 256 + t;
    int v = (i < N_NODES) ? g_degi[i] : 0;
    sh[t] = v;
    __syncthreads();
    for (int ofs = 1; ofs < 256; ofs <<= 1) {
        int u = (t >= ofs) ? sh[t - ofs] : 0;
        __syncthreads();
        sh[t] += u;
        __syncthreads();
    }
    if (i < N_NODES) {
        int excl = sh[t] - v + g_bpre[blockIdx.x];
        g_off[i] = excl;
        g_cur[i] = excl;
        g_dinv[i] = rsqrtf((float)v + 1.0f);
    }
}

__global__ void place_kernel(const int* __restrict__ ei) {
    int e = blockIdx.x * blockDim.x + threadIdx.x;
    if (e >= N_EDGES) return;
    int s = ei[e];
    int d = ei[N_EDGES + e];
    int pos = atomicAdd(&g_cur[d], 1);
    float nrm = g_dinv[s] * g_dinv[d];
    g_csr[pos] = make_int2(s, __float_as_int(nrm));
}

// ---------------- gather body (bf16 features, fp32 accumulate) ------------
__device__ __forceinline__ float4 f4fma(float4 a, float n, float4 v) {
    a.x += n * v.x; a.y += n * v.y; a.z += n * v.z; a.w += n * v.w;
    return a;
}

__device__ __forceinline__ float4 bf4(uint2 u) {
    __nv_bfloat162 b0 = *reinterpret_cast<__nv_bfloat162*>(&u.x);
    __nv_bfloat162 b1 = *reinterpret_cast<__nv_bfloat162*>(&u.y);
    float2 f0 = __bfloat1622float2(b0);
    float2 f1 = __bfloat1622float2(b1);
    return make_float4(f0.x, f0.y, f1.x, f1.y);
}

__device__ __forceinline__ float4 gather_body(const __nv_bfloat16* __restrict__ Xb,
                                              int node, int lane) {
    float di = g_dinv[node];
    float s  = di * di;
    float4 acc = bf4(((const uint2*)(Xb + (size_t)node * D))[lane]);
    acc.x *= s; acc.y *= s; acc.z *= s; acc.w *= s;

    int beg = g_off[node], end = g_off[node + 1];
    int j = beg;
    for (; j + 8 <= end; j += 8) {             // 8-wide independent load chains
        int2 e0 = g_csr[j + 0], e1 = g_csr[j + 1];
        int2 e2 = g_csr[j + 2], e3 = g_csr[j + 3];
        int2 e4 = g_csr[j + 4], e5 = g_csr[j + 5];
        int2 e6 = g_csr[j + 6], e7 = g_csr[j + 7];
        uint2 u0 = ((const uint2*)(Xb + (size_t)e0.x * D))[lane];
        uint2 u1 = ((const uint2*)(Xb + (size_t)e1.x * D))[lane];
        uint2 u2 = ((const uint2*)(Xb + (size_t)e2.x * D))[lane];
        uint2 u3 = ((const uint2*)(Xb + (size_t)e3.x * D))[lane];
        uint2 u4 = ((const uint2*)(Xb + (size_t)e4.x * D))[lane];
        uint2 u5 = ((const uint2*)(Xb + (size_t)e5.x * D))[lane];
        uint2 u6 = ((const uint2*)(Xb + (size_t)e6.x * D))[lane];
        uint2 u7 = ((const uint2*)(Xb + (size_t)e7.x * D))[lane];
        acc = f4fma(acc, __int_as_float(e0.y), bf4(u0));
        acc = f4fma(acc, __int_as_float(e1.y), bf4(u1));
        acc = f4fma(acc, __int_as_float(e2.y), bf4(u2));
        acc = f4fma(acc, __int_as_float(e3.y), bf4(u3));
        acc = f4fma(acc, __int_as_float(e4.y), bf4(u4));
        acc = f4fma(acc, __int_as_float(e5.y), bf4(u5));
        acc = f4fma(acc, __int_as_float(e6.y), bf4(u6));
        acc = f4fma(acc, __int_as_float(e7.y), bf4(u7));
    }
    for (; j + 2 <= end; j += 2) {
        int2 e0 = g_csr[j + 0], e1 = g_csr[j + 1];
        uint2 u0 = ((const uint2*)(Xb + (size_t)e0.x * D))[lane];
        uint2 u1 = ((const uint2*)(Xb + (size_t)e1.x * D))[lane];
        acc = f4fma(acc, __int_as_float(e0.y), bf4(u0));
        acc = f4fma(acc, __int_as_float(e1.y), bf4(u1));
    }
    if (j < end) {
        int2 e = g_csr[j];
        uint2 u = ((const uint2*)(Xb + (size_t)e.x * D))[lane];
        acc = f4fma(acc, __int_as_float(e.y), bf4(u));
    }
    return acc;
}

// ---------------- FUSED gather + tensor-core GEMM -------------------------
// Block: 256 thr, 64 nodes. Phase 1: stage W (tf32, pitch 136) + gather the
// block's 64 rows into smem (tf32, pitch 132 -> conflict-free fragments).
// Phase 2: m16n8k8 tf32 MMA, warp tile 16x64; epilogue bias+relu+bf16.
#define SW_PITCH 136
#define SA_PITCH 132
#define SMEM_FUSED ((D * SW_PITCH + 64 * SA_PITCH) * 4)

#define MMA_TF32(d, a0, a1, a2, a3, b0, b1) \
    asm volatile("mma.sync.aligned.m16n8k8.row.col.f32.tf32.tf32.f32 " \
                 "{%0,%1,%2,%3}, {%4,%5,%6,%7}, {%8,%9}, {%0,%1,%2,%3};" \
                 : "+f"(d[0]), "+f"(d[1]), "+f"(d[2]), "+f"(d[3]) \
                 : "r"(a0), "r"(a1), "r"(a2), "r"(a3), "r"(b0), "r"(b1))

__device__ __forceinline__ unsigned tf32(float f) {
    unsigned u;
    asm("cvt.rna.tf32.f32 %0, %1;" : "=r"(u) : "f"(f));
    return u;
}

__global__ void gather_gemm_kernel(const __nv_bfloat16* __restrict__ Xb,
                                   const float* __restrict__ W,
                                   const float* __restrict__ bias,
                                   __nv_bfloat16* __restrict__ Yb) {
    extern __shared__ unsigned smem[];
    unsigned* sW = smem;                       // [D][SW_PITCH]
    unsigned* sA = smem + D * SW_PITCH;        // [64][SA_PITCH]
    int tid = threadIdx.x;
    int warp = tid >> 5, lane = tid & 31;

    for (int i = tid; i < D * D; i += 256) {   // stage W
        int k = i >> 7, n = i & 127;
        sW[k * SW_PITCH + n] = tf32(W[i]);
    }

    int base = blockIdx.x * 64;
#pragma unroll 1
    for (int i = 0; i < 8; i++) {              // gather 8 nodes per warp
        int nl = warp * 8 + i;
        int node = base + nl;
        float4 acc = (node < N_NODES) ? gather_body(Xb, node, lane)
                                      : make_float4(0.f, 0.f, 0.f, 0.f);
        unsigned* dst = &sA[nl * SA_PITCH + lane * 4];
        dst[0] = tf32(acc.x); dst[1] = tf32(acc.y);
        dst[2] = tf32(acc.z); dst[3] = tf32(acc.w);
    }
    __syncthreads();

    int row0 = (warp & 3) * 16;
    int col0 = (warp >> 2) * 64;
    int grp = lane >> 2, thr = lane & 3;

    float acc[8][4];
#pragma unroll
    for (int nt = 0; nt < 8; nt++)
#pragma unroll
        for (int c = 0; c < 4; c++) acc[nt][c] = 0.0f;

    const unsigned* Ab = &sA[(row0 + grp) * SA_PITCH];
#pragma unroll 2
    for (int k0 = 0; k0 < D; k0 += 8) {
        unsigned a0 = Ab[k0 + thr];
        unsigned a1 = Ab[8 * SA_PITCH + k0 + thr];
        unsigned a2 = Ab[k0 + thr + 4];
        unsigned a3 = Ab[8 * SA_PITCH + k0 + thr + 4];
#pragma unroll
        for (int nt = 0; nt < 8; nt++) {
            unsigned b0 = sW[(k0 + thr) * SW_PITCH + col0 + nt * 8 + grp];
            unsigned b1 = sW[(k0 + thr + 4) * SW_PITCH + col0 + nt * 8 + grp];
            MMA_TF32(acc[nt], a0, a1, a2, a3, b0, b1);
        }
    }

    size_t r0 = base + row0 + grp, r1 = r0 + 8;
#pragma unroll
    for (int nt = 0; nt < 8; nt++) {
        int c = col0 + nt * 8 + 2 * thr;
        float bv0 = bias[c], bv1 = bias[c + 1];
        float y00 = fmaxf(acc[nt][0] + bv0, 0.0f);
        float y01 = fmaxf(acc[nt][1] + bv1, 0.0f);
        float y10 = fmaxf(acc[nt][2] + bv0, 0.0f);
        float y11 = fmaxf(acc[nt][3] + bv1, 0.0f);
        __nv_bfloat162 p0 = __float22bfloat162_rn(make_float2(y00, y01));
        __nv_bfloat162 p1 = __float22bfloat162_rn(make_float2(y10, y11));
        *(unsigned*)(Yb + r0 * D + c) = *reinterpret_cast<unsigned*>(&p0);
        *(unsigned*)(Yb + r1 * D + c) = *reinterpret_cast<unsigned*>(&p1);
    }
}

// last layer: gather + pool (smem block reduction, one atomic warp per
// interior block; batch sorted so ~99% of blocks are uniform)
__global__ void gather_pool_kernel(const __nv_bfloat16* __restrict__ Xb,
                                   const int* __restrict__ batch) {
    __shared__ float sred[8][D];               // 4 KB
    int warp = threadIdx.x >> 5;
    int node = blockIdx.x * 8 + warp;
    int lane = threadIdx.x & 31;
    float4 acc = gather_body(Xb, node, lane);

    int g0 = batch[blockIdx.x * 8];
    int g7 = batch[blockIdx.x * 8 + 7];
    if (g0 == g7) {
        ((float4*)sred[warp])[lane] = acc;
        __syncthreads();
        if (warp == 0) {
            float4 s = make_float4(0.f, 0.f, 0.f, 0.f);
#pragma unroll
            for (int w = 0; w < 8; w++) {
                float4 v = ((float4*)sred[w])[lane];
                s.x += v.x; s.y += v.y; s.z += v.z; s.w += v.w;
            }
            float* p = &g_sums[g0 * D + lane * 4];
            atomicAdd(p + 0, s.x);
            atomicAdd(p + 1, s.y);
            atomicAdd(p + 2, s.z);
            atomicAdd(p + 3, s.w);
        }
    } else {
        int g = batch[node];
        float* p = &g_sums[g * D + lane * 4];
        atomicAdd(p + 0, acc.x);
        atomicAdd(p + 1, acc.y);
        atomicAdd(p + 2, acc.z);
        atomicAdd(p + 3, acc.w);
    }
}

// ---------------- head: S·W2/cnt + b2 -> linear -> softmax ----------------
__global__ void head_kernel(const float* __restrict__ W2,
                            const float* __restrict__ b2,
                            const float* __restrict__ lin_W,
                            const float* __restrict__ lin_b,
                            float* __restrict__ out) {
    __shared__ float sp[D];
    __shared__ float sl[N_CLASSES];
    int g = blockIdx.x;
    int c = threadIdx.x;
    int cnt = g_end[g] - (g > 0 ? g_end[g - 1] : 0);
    float inv = 1.0f / fmaxf((float)cnt, 1.0f);

    float acc = 0.0f;
    for (int k = 0; k < D; k++)
        acc += g_sums[g * D + k] * W2[k * D + c];
    sp[c] = acc * inv + b2[c];
    __syncthreads();

    if (c < N_CLASSES) {
        float l = lin_b[c];
        for (int k = 0; k < D; k++)
            l += sp[k] * lin_W[k * N_CLASSES + c];
        sl[c] = l;
    }
    __syncthreads();

    if (c == 0) {
        float m = sl[0];
#pragma unroll
        for (int j = 1; j < N_CLASSES; j++) m = fmaxf(m, sl[j]);
        float e[N_CLASSES], ssum = 0.0f;
#pragma unroll
        for (int j = 0; j < N_CLASSES; j++) { e[j] = expf(sl[j] - m); ssum += e[j]; }
        float isum = 1.0f / ssum;
#pragma unroll
        for (int j = 0; j < N_CLASSES; j++)
            out[g * N_CLASSES + j] = e[j] * isum;
    }
}

// ---------------- launch ----------------
extern "C" void kernel_launch(void* const* d_in, const int* in_sizes, int n_in,
                              void* d_out, int out_size) {
    const float* x     = (const float*)d_in[0];
    const int*   ei    = (const int*)d_in[1];    // int32 (JAX x64 disabled)
    const int*   batch = (const int*)d_in[2];
    const float* W0    = (const float*)d_in[3];
    const float* b0    = (const float*)d_in[4];
    const float* W1    = (const float*)d_in[5];
    const float* b1    = (const float*)d_in[6];
    const float* W2    = (const float*)d_in[7];
    const float* b2    = (const float*)d_in[8];
    const float* lW    = (const float*)d_in[9];
    const float* lb    = (const float*)d_in[10];
    float* out = (float*)d_out;

    void *p0, *p1;
    cudaGetSymbolAddress(&p0, g_fb0);
    cudaGetSymbolAddress(&p1, g_fb1);
    __nv_bfloat16* Fb0 = (__nv_bfloat16*)p0;
    __nv_bfloat16* Fb1 = (__nv_bfloat16*)p1;

    cudaFuncSetAttribute(gather_gemm_kernel,
                         cudaFuncAttributeMaxDynamicSharedMemorySize,
                         SMEM_FUSED);

    const int NT = 256;
    const int node_blocks = (N_NODES + NT - 1) / NT;      // 391
    const int edge_blocks = (N_EDGES + NT - 1) / NT;
    const int fuse_blocks = N_PAD / 64;                   // 1563
    const int gath_blocks = N_NODES / 8;                  // warp/node, 8/block
    const int prep_blocks = (N_NODES * 32 + NT - 1) / NT; // 12500

    // CSR build + bookkeeping (graph-capturable, deterministic)
    prep_kernel<<<prep_blocks, NT>>>(batch, x, Fb0);
    hist_kernel<<<edge_blocks, NT>>>(ei + N_EDGES);
    blockred_kernel<<<node_blocks, NT>>>();
    bscan_kernel<<<1, 512>>>();
    blockscan_kernel<<<node_blocks, NT>>>();
    place_kernel<<<edge_blocks, NT>>>(ei);

    // layer 0: Fb1 = bf16(relu(agg(Fb0) W0 + b0))    (fused)
    gather_gemm_kernel<<<fuse_blocks, NT, SMEM_FUSED>>>(Fb0, W0, b0, Fb1);

    // layer 1: Fb0 = bf16(relu(agg(Fb1) W1 + b1))    (fused)
    gather_gemm_kernel<<<fuse_blocks, NT, SMEM_FUSED>>>(Fb1, W1, b1, Fb0);

    // layer 2 (projection folded into head): S = pool(agg(Fb0))
    gather_pool_kernel<<<gath_blocks, NT>>>(Fb0, batch);

    head_kernel<<<N_GRAPHS, D>>>(W2, b2, lW, lb, out);
}